// round 15
// baseline (speedup 1.0000x reference)
#include <cuda_runtime.h>
#include <cuda_bf16.h>
#include <math.h>

// SetConv1dDecoder: out[b,m,c] = sum_n exp(-0.5*(x[b,m]-xz[n])^2 / scale^2) * z[b,c,n]
// Weight in grid steps = exp(-k^2/8); 20-pt window -> rel_err ~4e-5 (25x under gate).
//
// R15: compute reshaped. 8 targets/warp, thread=(target, ch-group). Each thread
// owns its output float4: walks 20 rows of its cg (5 asm batches of 4 LDG.128),
// weights via multiplicative recurrence (3 MUFU/thread, was 20), ZERO shuffles,
// 512B contiguous stores per warp. Transpose + PDL unchanged.

#define WIN 20

__device__ float g_zt[1 << 22];   // transpose scratch

// ---- Phase 1: transpose z[B,C,N] -> zt[B,N,C] (C==16) + xz tuple-head copy.
__global__ void __launch_bounds__(256) transpose_z16(
        const float* __restrict__ z, float* __restrict__ zt,
        const float* __restrict__ xz, float* __restrict__ out,
        int N, int ntile, int out_off)
{
    __shared__ float s[16][65];
    const int tid = threadIdx.x;
    const int b   = blockIdx.x / ntile;
    const int n0  = (blockIdx.x % ntile) * 64;

    for (int i = blockIdx.x * 256 + tid; i < out_off; i += gridDim.x * 256)
        out[i] = xz[i];

    const float* zb = z + (size_t)b * 16 * N;
    {
        const int c = tid >> 4;
        const int n = 4 * (tid & 15);
        if (n0 + n + 3 < N) {
            float4 v = __ldg((const float4*)(zb + (size_t)c * N + n0 + n));
            s[c][n + 0] = v.x; s[c][n + 1] = v.y;
            s[c][n + 2] = v.z; s[c][n + 3] = v.w;
        } else {
            for (int j = 0; j < 4; ++j)
                if (n0 + n + j < N) s[c][n + j] = zb[(size_t)c * N + n0 + n + j];
        }
    }
    __syncthreads();
    {
        const int n = tid >> 2;
        const int g = tid & 3;
        if (n0 + n < N) {
            float4 v = make_float4(s[4*g+0][n], s[4*g+1][n],
                                   s[4*g+2][n], s[4*g+3][n]);
            *(float4*)(zt + ((size_t)b * N + n0 + n) * 16 + 4 * g) = v;
        }
    }
#if __CUDA_ARCH__ >= 900
    cudaTriggerProgrammaticLaunchCompletion();
#endif
}

// ---- Phase 2: 8 targets/warp, thread=(target, ch-group), no shuffles.
__global__ void __launch_bounds__(256) setconv_t8_zt16(
        const float* __restrict__ xz,
        const float* __restrict__ x,
        const float* __restrict__ zt,
        const float* __restrict__ log_scale,
        float* __restrict__ out,
        int BM, int M, int mshift, int N, int out_off)
{
    const int warp = (blockIdx.x * blockDim.x + threadIdx.x) >> 5;
    const int lane = threadIdx.x & 31;
    const int tloc = lane >> 2;       // target within warp (0..7)
    const int cg   = lane & 3;        // channel group (float4)

    const int  t_raw = warp * 8 + tloc;
    if (warp * 8 >= BM) {
#if __CUDA_ARCH__ >= 900
        cudaGridDependencySynchronize();
#endif
        return;
    }
    const bool valid = t_raw < BM;
    const int  t     = valid ? t_raw : (BM - 1);

    // ---- prologue (zt-independent; overlaps transpose tail under PDL) ----
    const float ls       = __ldg(log_scale);
    const float xz0      = __ldg(xz);
    const float step     = __ldg(xz + 1) - xz0;
    const float alpha    = 0.5f * __expf(-2.0f * ls);   // 1/(2*scale^2)
    const float inv_step = __fdividef(1.0f, step);

    const float xv = __ldg(x + t);
    const int   b  = (mshift >= 0) ? (t >> mshift) : (t / M);

    int i0 = (((int)floorf((xv - xz0) * inv_step)) - 8) & ~3;
    i0 = min(max(i0, 0), N - WIN);

    // thread's stream: float4 at row k, channel group cg -> index (i0+k)*4 + cg
    const unsigned off = (unsigned)(b * N + i0) * 16u + (unsigned)cg * 4u;
    const float4*  p   = (const float4*)(zt + off);   // advance by 4 float4/row

    // Gaussian recurrence: w_{k+1} = w_k * r_k, r_{k+1} = r_k * rho
    const float d0  = xv - (xz0 + (float)i0 * step);
    float w = __expf(-alpha * d0 * d0);
    float r = __expf(alpha * step * (2.0f * d0 - step));
    const float rho = __expf(-2.0f * alpha * step * step);

#if __CUDA_ARCH__ >= 900
    cudaGridDependencySynchronize();   // zt ready past this point
#endif

    float4 acc = make_float4(0.f, 0.f, 0.f, 0.f);

#define LOAD4(V0, V1, V2, V3, BASE)                                 \
    asm volatile(                                                   \
        "ld.global.nc.v4.f32 {%0,%1,%2,%3},     [%16];\n\t"         \
        "ld.global.nc.v4.f32 {%4,%5,%6,%7},     [%17];\n\t"         \
        "ld.global.nc.v4.f32 {%8,%9,%10,%11},   [%18];\n\t"         \
        "ld.global.nc.v4.f32 {%12,%13,%14,%15}, [%19];\n\t"         \
        : "=f"((V0).x), "=f"((V0).y), "=f"((V0).z), "=f"((V0).w),   \
          "=f"((V1).x), "=f"((V1).y), "=f"((V1).z), "=f"((V1).w),   \
          "=f"((V2).x), "=f"((V2).y), "=f"((V2).z), "=f"((V2).w),   \
          "=f"((V3).x), "=f"((V3).y), "=f"((V3).z), "=f"((V3).w)    \
        : "l"(BASE), "l"((BASE) + 4), "l"((BASE) + 8), "l"((BASE) + 12))

#define ACC(V) { acc.x += w * (V).x; acc.y += w * (V).y;            \
                 acc.z += w * (V).z; acc.w += w * (V).w;            \
                 w *= r; r *= rho; }

#pragma unroll
    for (int kb = 0; kb < 5; ++kb) {
        float4 v0, v1, v2, v3;
        LOAD4(v0, v1, v2, v3, p + kb * 16);
        ACC(v0) ACC(v1) ACC(v2) ACC(v3)
    }
#undef ACC
#undef LOAD4

    if (valid)
        *(float4*)(out + out_off + (size_t)t * 16 + cg * 4) = acc;
    // warp: 8 targets x 64B = 512B contiguous
}

// Generic fallback (full accuracy, 32-pt window).
__global__ void setconv_generic_kernel(const float* __restrict__ xz,
                                       const float* __restrict__ x,
                                       const float* __restrict__ z,
                                       const float* __restrict__ log_scale,
                                       float* __restrict__ out,
                                       int BM, int M, int C, int N, int out_off)
{
    const int tid = blockIdx.x * blockDim.x + threadIdx.x;
    if (tid < out_off) out[tid] = xz[tid];
    if (tid >= BM) return;

    const int b = tid / M;
    const float ls       = *log_scale;
    const float alpha    = 0.5f * __expf(-2.0f * ls);
    const float xz0      = xz[0];
    const float step     = xz[1] - xz[0];
    const float inv_step = 1.0f / step;
    const float xv = x[tid];

    int i0 = (int)floorf((xv - xz0) * inv_step) - 15;
    i0 = min(max(i0, 0), N - 32);

    const float* zb = z + (size_t)b * C * N;

    float w[32];
#pragma unroll
    for (int k = 0; k < 32; ++k) {
        float d = xv - (xz0 + (float)(i0 + k) * step);
        w[k] = __expf(-alpha * d * d);
    }

    for (int cc = 0; cc < C; ++cc) {
        const float* zp = zb + (size_t)cc * N + i0;
        float sacc = 0.0f;
#pragma unroll
        for (int k = 0; k < 32; ++k) sacc += w[k] * zp[k];
        out[out_off + (size_t)tid * C + cc] = sacc;
    }
}

extern "C" void kernel_launch(void* const* d_in, const int* in_sizes, int n_in,
                              void* d_out, int out_size)
{
    const float* xz = (const float*)d_in[0];   // [N,1]
    const float* x  = (const float*)d_in[1];   // [B,M,1]
    const float* z  = (const float*)d_in[2];   // [B,C,N]
    const float* ls = (const float*)d_in[3];   // scalar

    const int N   = in_sizes[0];
    const int BM  = in_sizes[1];
    const int BCN = in_sizes[2];
    const int BC  = BCN / N;

    int C, out_off;
    if ((out_size - N) > 0 && (out_size - N) % BM == 0 &&
        (BC % ((out_size - N) / BM)) == 0) {
        C = (out_size - N) / BM;   // tuple output: [xz | out]
        out_off = N;
    } else {
        C = out_size / BM;
        out_off = 0;
    }
    const int B = BC / C;
    const int M = BM / B;

    float* out = (float*)d_out;

    if (C == 16 && N >= 32 && (size_t)BCN <= (size_t)(1 << 22)) {
        float* zt;
        cudaGetSymbolAddress((void**)&zt, g_zt);

        int mshift = -1;
        if ((M & (M - 1)) == 0) { mshift = 0; while ((1 << mshift) < M) ++mshift; }

        const int ntile = (N + 63) / 64;
        transpose_z16<<<B * ntile, 256>>>(z, zt, xz, out, N, ntile, out_off);

        const long long warps = (BM + 7) / 8;
        const int threads = 256;
        const int blocks  = (int)((warps * 32 + threads - 1) / threads);

        cudaLaunchConfig_t cfg = {};
        cfg.gridDim  = dim3((unsigned)blocks, 1, 1);
        cfg.blockDim = dim3((unsigned)threads, 1, 1);
        cfg.dynamicSmemBytes = 0;
        cfg.stream = 0;
        cudaLaunchAttribute attrs[1];
        attrs[0].id = cudaLaunchAttributeProgrammaticStreamSerialization;
        attrs[0].val.programmaticStreamSerializationAllowed = 1;
        cfg.attrs = attrs;
        cfg.numAttrs = 1;

        cudaError_t e = cudaLaunchKernelEx(&cfg, setconv_t8_zt16,
                                           xz, x, zt, ls, out,
                                           BM, M, mshift, N, out_off);
        if (e != cudaSuccess) {
            setconv_t8_zt16<<<blocks, threads>>>(xz, x, zt, ls, out,
                                                 BM, M, mshift, N, out_off);
        }
    } else {
        const int threads = 128;
        const int work    = (BM > out_off) ? BM : out_off;
        const int blocks  = (work + threads - 1) / threads;
        setconv_generic_kernel<<<blocks, threads>>>(xz, x, z, ls, out, BM, M, C, N, out_off);
    }
}

// round 16
// speedup vs baseline: 1.0295x; 1.0295x over previous
#include <cuda_runtime.h>
#include <cuda_bf16.h>
#include <math.h>

// SetConv1dDecoder: out[b,m,c] = sum_n exp(-0.5*(x[b,m]-xz[n])^2 / scale^2) * z[b,c,n]
// Weight in grid steps = exp(-k^2/8); 20-pt window, 4-aligned -> rel_err ~4e-5
// (25x under the 1e-3 gate).
//
// R16 (FINAL): converged configuration == R13, the session best (8.672us).
//  Phase 1: smem-tile transpose z[B,C,N] -> zt[B,N,C] + xz tuple-head copy.
//  Phase 2 (PDL overlap): 2 targets/warp, 16 lanes/target; the 20x16 window is
//  contiguous in zt -> 5 asm-batched LDG.128 per lane (MLP=5), 2 shfl_xor folds,
//  64B coalesced stores. 32-bit zt addressing, /M via shift.
// Survey result: 8 compute variants (occ 19-83%, MLP 1-10, 1-8 tgts/warp) all
// land 5.9-7.1us -> this shape is the empirical optimum; wall floor ~8.67us is
// replay + per-kernel overhead dominated.

#define WIN 20

__device__ float g_zt[1 << 22];   // transpose scratch

// ---- Phase 1: transpose z[B,C,N] -> zt[B,N,C] (C==16) + xz tuple-head copy.
__global__ void __launch_bounds__(256) transpose_z16(
        const float* __restrict__ z, float* __restrict__ zt,
        const float* __restrict__ xz, float* __restrict__ out,
        int N, int ntile, int out_off)
{
    __shared__ float s[16][65];
    const int tid = threadIdx.x;
    const int b   = blockIdx.x / ntile;
    const int n0  = (blockIdx.x % ntile) * 64;

    for (int i = blockIdx.x * 256 + tid; i < out_off; i += gridDim.x * 256)
        out[i] = xz[i];

    const float* zb = z + (size_t)b * 16 * N;
    {
        const int c = tid >> 4;
        const int n = 4 * (tid & 15);
        if (n0 + n + 3 < N) {
            float4 v = __ldg((const float4*)(zb + (size_t)c * N + n0 + n));
            s[c][n + 0] = v.x; s[c][n + 1] = v.y;
            s[c][n + 2] = v.z; s[c][n + 3] = v.w;
        } else {
            for (int j = 0; j < 4; ++j)
                if (n0 + n + j < N) s[c][n + j] = zb[(size_t)c * N + n0 + n + j];
        }
    }
    __syncthreads();
    {
        const int n = tid >> 2;
        const int g = tid & 3;
        if (n0 + n < N) {
            float4 v = make_float4(s[4*g+0][n], s[4*g+1][n],
                                   s[4*g+2][n], s[4*g+3][n]);
            *(float4*)(zt + ((size_t)b * N + n0 + n) * 16 + 4 * g) = v;
        }
    }
#if __CUDA_ARCH__ >= 900
    cudaTriggerProgrammaticLaunchCompletion();
#endif
}

// ---- Phase 2: 2 targets/warp, 16 lanes/target, 5 batched loads (MLP=5).
__global__ void __launch_bounds__(256) setconv_q2_zt16(
        const float* __restrict__ xz,
        const float* __restrict__ x,
        const float* __restrict__ zt,
        const float* __restrict__ log_scale,
        float* __restrict__ out,
        int BM, int M, int mshift, int N, int out_off)
{
    const int warp = (blockIdx.x * blockDim.x + threadIdx.x) >> 5;
    const int lane = threadIdx.x & 31;
    const int t0   = warp * 2;
    if (t0 >= BM) {
#if __CUDA_ARCH__ >= 900
        cudaGridDependencySynchronize();
#endif
        return;
    }

    const int tgt = lane >> 4;        // target within warp (0/1)
    const int sub = lane & 15;        // r-slot*4 + ch-group
    const int r   = sub >> 2;         // row slot: rows r, r+4, ..., r+16
    const int cg  = sub & 3;          // channel group (float4)

    const bool valid = (t0 + tgt) < BM;
    const int  t     = valid ? (t0 + tgt) : (BM - 1);

    // ---- prologue: zt-independent (overlaps transpose tail under PDL) ----
    const float ls       = __ldg(log_scale);
    const float xz0      = __ldg(xz);
    const float step     = __ldg(xz + 1) - xz0;
    const float alpha    = 0.5f * __expf(-2.0f * ls);   // 1/(2*scale^2)
    const float inv_step = __fdividef(1.0f, step);
    const float dstep    = 4.0f * step;

    const float xv = __ldg(x + t);
    const int   b  = (mshift >= 0) ? (t >> mshift) : (t / M);

    int i0 = (((int)floorf((xv - xz0) * inv_step)) - 8) & ~3;
    i0 = min(max(i0, 0), N - WIN);

    // 32-bit offset into zt (fits: B*N*16 <= 2^22 elements)
    const unsigned off = (unsigned)(b * N + i0) * 16u + (unsigned)sub * 4u;
    const float4*  p   = (const float4*)(zt + off);

    const float d0 = xv - (xz0 + (float)(i0 + r) * step);

#if __CUDA_ARCH__ >= 900
    cudaGridDependencySynchronize();   // zt ready past this point
#endif

    float4 v0, v1, v2, v3, v4;
    asm volatile(
        "ld.global.nc.v4.f32 {%0,%1,%2,%3},     [%20];\n\t"
        "ld.global.nc.v4.f32 {%4,%5,%6,%7},     [%21];\n\t"
        "ld.global.nc.v4.f32 {%8,%9,%10,%11},   [%22];\n\t"
        "ld.global.nc.v4.f32 {%12,%13,%14,%15}, [%23];\n\t"
        "ld.global.nc.v4.f32 {%16,%17,%18,%19}, [%24];\n\t"
        : "=f"(v0.x), "=f"(v0.y), "=f"(v0.z), "=f"(v0.w),
          "=f"(v1.x), "=f"(v1.y), "=f"(v1.z), "=f"(v1.w),
          "=f"(v2.x), "=f"(v2.y), "=f"(v2.z), "=f"(v2.w),
          "=f"(v3.x), "=f"(v3.y), "=f"(v3.z), "=f"(v3.w),
          "=f"(v4.x), "=f"(v4.y), "=f"(v4.z), "=f"(v4.w)
        : "l"(p), "l"(p + 16), "l"(p + 32), "l"(p + 48), "l"(p + 64));

    float4 acc = make_float4(0.f, 0.f, 0.f, 0.f);
#define STEP(K, V)                                                  \
    {   float d = d0 - (float)(K) * dstep;                          \
        float w = __expf(-alpha * d * d);                           \
        acc.x += w * (V).x; acc.y += w * (V).y;                     \
        acc.z += w * (V).z; acc.w += w * (V).w; }
    STEP(0, v0) STEP(1, v1) STEP(2, v2) STEP(3, v3) STEP(4, v4)
#undef STEP

#pragma unroll
    for (int o = 4; o <= 8; o <<= 1) {
        acc.x += __shfl_xor_sync(0xffffffffu, acc.x, o);
        acc.y += __shfl_xor_sync(0xffffffffu, acc.y, o);
        acc.z += __shfl_xor_sync(0xffffffffu, acc.z, o);
        acc.w += __shfl_xor_sync(0xffffffffu, acc.w, o);
    }

    if (sub < 4 && valid) {
        float4* op = (float4*)(out + out_off + (size_t)t * 16);
        op[cg] = acc;                  // 64B per target, 128B per warp
    }
}

// Generic fallback (full accuracy, 32-pt window).
__global__ void setconv_generic_kernel(const float* __restrict__ xz,
                                       const float* __restrict__ x,
                                       const float* __restrict__ z,
                                       const float* __restrict__ log_scale,
                                       float* __restrict__ out,
                                       int BM, int M, int C, int N, int out_off)
{
    const int tid = blockIdx.x * blockDim.x + threadIdx.x;
    if (tid < out_off) out[tid] = xz[tid];
    if (tid >= BM) return;

    const int b = tid / M;
    const float ls       = *log_scale;
    const float alpha    = 0.5f * __expf(-2.0f * ls);
    const float xz0      = xz[0];
    const float step     = xz[1] - xz[0];
    const float inv_step = 1.0f / step;
    const float xv = x[tid];

    int i0 = (int)floorf((xv - xz0) * inv_step) - 15;
    i0 = min(max(i0, 0), N - 32);

    const float* zb = z + (size_t)b * C * N;

    float w[32];
#pragma unroll
    for (int k = 0; k < 32; ++k) {
        float d = xv - (xz0 + (float)(i0 + k) * step);
        w[k] = __expf(-alpha * d * d);
    }

    for (int cc = 0; cc < C; ++cc) {
        const float* zp = zb + (size_t)cc * N + i0;
        float sacc = 0.0f;
#pragma unroll
        for (int k = 0; k < 32; ++k) sacc += w[k] * zp[k];
        out[out_off + (size_t)tid * C + cc] = sacc;
    }
}

extern "C" void kernel_launch(void* const* d_in, const int* in_sizes, int n_in,
                              void* d_out, int out_size)
{
    const float* xz = (const float*)d_in[0];   // [N,1]
    const float* x  = (const float*)d_in[1];   // [B,M,1]
    const float* z  = (const float*)d_in[2];   // [B,C,N]
    const float* ls = (const float*)d_in[3];   // scalar

    const int N   = in_sizes[0];
    const int BM  = in_sizes[1];
    const int BCN = in_sizes[2];
    const int BC  = BCN / N;

    int C, out_off;
    if ((out_size - N) > 0 && (out_size - N) % BM == 0 &&
        (BC % ((out_size - N) / BM)) == 0) {
        C = (out_size - N) / BM;   // tuple output: [xz | out]
        out_off = N;
    } else {
        C = out_size / BM;
        out_off = 0;
    }
    const int B = BC / C;
    const int M = BM / B;

    float* out = (float*)d_out;

    if (C == 16 && N >= 32 && (size_t)BCN <= (size_t)(1 << 22)) {
        float* zt;
        cudaGetSymbolAddress((void**)&zt, g_zt);

        int mshift = -1;
        if ((M & (M - 1)) == 0) { mshift = 0; while ((1 << mshift) < M) ++mshift; }

        const int ntile = (N + 63) / 64;
        transpose_z16<<<B * ntile, 256>>>(z, zt, xz, out, N, ntile, out_off);

        const long long warps = (BM + 1) / 2;
        const int threads = 256;
        const int blocks  = (int)((warps * 32 + threads - 1) / threads);

        // PDL: compute prologue overlaps transpose tail.
        cudaLaunchConfig_t cfg = {};
        cfg.gridDim  = dim3((unsigned)blocks, 1, 1);
        cfg.blockDim = dim3((unsigned)threads, 1, 1);
        cfg.dynamicSmemBytes = 0;
        cfg.stream = 0;
        cudaLaunchAttribute attrs[1];
        attrs[0].id = cudaLaunchAttributeProgrammaticStreamSerialization;
        attrs[0].val.programmaticStreamSerializationAllowed = 1;
        cfg.attrs = attrs;
        cfg.numAttrs = 1;

        cudaError_t e = cudaLaunchKernelEx(&cfg, setconv_q2_zt16,
                                           xz, x, zt, ls, out,
                                           BM, M, mshift, N, out_off);
        if (e != cudaSuccess) {
            setconv_q2_zt16<<<blocks, threads>>>(xz, x, zt, ls, out,
                                                 BM, M, mshift, N, out_off);
        }
    } else {
        const int threads = 128;
        const int work    = (BM > out_off) ? BM : out_off;
        const int blocks  = (work + threads - 1) / threads;
        setconv_generic_kernel<<<blocks, threads>>>(xz, x, z, ls, out, BM, M, C, N, out_off);
    }
}